// round 1
// baseline (speedup 1.0000x reference)
#include <cuda_runtime.h>

#define NN 50000
#define NE 800000
#define ALPHA 0.5f

// ---------------- scratch (device globals; no runtime allocation) -----------
__device__ int   g_deg[2 * NN];      // [0,NN): out-deg (fwd lists), [NN,2NN): in-deg (bwd lists)
__device__ int   g_off[2 * NN];      // exclusive scan of g_deg (concatenated)
__device__ int   g_cur[2 * NN];      // fill cursors
__device__ float g_dinv[2 * NN];     // deg^-1/2 (0 if deg==0)
__device__ int   g_adj[2 * NE];      // fwd lists in [0,E), bwd lists in [E,2E)
__device__ float g_y[(size_t)NN * 256]; // y = [alpha*x@Wsrc | (1-alpha)*x@Wdst]
__device__ int   g_part[256];        // scan partials

// ---------------- init / degree count ---------------------------------------
__global__ void k_zero(int twoN) {
    int i = blockIdx.x * blockDim.x + threadIdx.x;
    if (i < twoN) g_deg[i] = 0;
}

__global__ void k_count(const int* __restrict__ row, const int* __restrict__ col,
                        int E, int N) {
    int e = blockIdx.x * blockDim.x + threadIdx.x;
    if (e < E) {
        atomicAdd(&g_deg[row[e]], 1);
        atomicAdd(&g_deg[N + col[e]], 1);
    }
}

// ---------------- block exclusive scan helper --------------------------------
__device__ __forceinline__ int block_exscan(int val, int nwarps) {
    __shared__ int ws[16];
    int lane = threadIdx.x & 31, w = threadIdx.x >> 5;
    int inc = val;
#pragma unroll
    for (int d = 1; d < 32; d <<= 1) {
        int t = __shfl_up_sync(0xffffffffu, inc, d);
        if (lane >= d) inc += t;
    }
    if (lane == 31) ws[w] = inc;
    __syncthreads();
    if (w == 0) {
        int s = (lane < nwarps) ? ws[lane] : 0;
#pragma unroll
        for (int d = 1; d < 16; d <<= 1) {
            int t = __shfl_up_sync(0xffffffffu, s, d);
            if (lane >= d) s += t;
        }
        if (lane < nwarps) ws[lane] = s;
    }
    __syncthreads();
    int pre = (w > 0) ? ws[w - 1] : 0;
    return pre + inc - val;
}

__global__ void k_scan1(int twoN) {  // 512 threads
    int i = blockIdx.x * 512 + threadIdx.x;
    int v = (i < twoN) ? g_deg[i] : 0;
    int ex = block_exscan(v, 16);
    if (i < twoN) g_off[i] = ex;
    if (threadIdx.x == 511) g_part[blockIdx.x] = ex + v;
}

__global__ void k_scan2(int nb) {    // 1 block, 256 threads
    int t = threadIdx.x;
    int v = (t < nb) ? g_part[t] : 0;
    int ex = block_exscan(v, 8);
    if (t < nb) g_part[t] = ex;
}

__global__ void k_scan3(int twoN) {  // 512 threads, same grid as k_scan1
    int i = blockIdx.x * 512 + threadIdx.x;
    if (i < twoN) {
        int o = g_off[i] + g_part[blockIdx.x];
        g_off[i] = o;
        g_cur[i] = o;
        int d = g_deg[i];
        g_dinv[i] = (d > 0) ? rsqrtf((float)d) : 0.0f;
    }
}

// ---------------- CSR fill ----------------------------------------------------
__global__ void k_fill(const int* __restrict__ row, const int* __restrict__ col,
                       int E, int N) {
    int e = blockIdx.x * blockDim.x + threadIdx.x;
    if (e < E) {
        int r = row[e], c = col[e];
        int p = atomicAdd(&g_cur[r], 1);
        g_adj[p] = c;
        int q = atomicAdd(&g_cur[N + c], 1);
        g_adj[q] = r;
    }
}

// ---------------- GEMM: y[M,256] = x[M,128] @ [a*Wsrc | (1-a)*Wdst] ----------
__global__ __launch_bounds__(256) void k_gemm(const float* __restrict__ X,
                                              const float* __restrict__ Ws,
                                              const float* __restrict__ Wd,
                                              int M) {
    __shared__ float As[64][32];
    __shared__ float Bs[32][256];
    int t  = threadIdx.x;
    int tx = t & 31;   // column group: cols tx*4..+4 and 128+tx*4..+4
    int ty = t >> 5;   // row group: rows ty*8..+8
    int m0 = blockIdx.x * 64;
    float acc[8][8];
#pragma unroll
    for (int i = 0; i < 8; i++)
#pragma unroll
        for (int j = 0; j < 8; j++) acc[i][j] = 0.0f;

    for (int kk = 0; kk < 128; kk += 32) {
        // load A tile 64x32 (2 float4 per thread)
#pragma unroll
        for (int i = 0; i < 2; i++) {
            int f4 = i * 256 + t;
            int ar = f4 >> 3, ac = (f4 & 7) << 2;
            float4 v = make_float4(0.f, 0.f, 0.f, 0.f);
            int m = m0 + ar;
            if (m < M) v = *(const float4*)(X + (size_t)m * 128 + kk + ac);
            *(float4*)&As[ar][ac] = v;
        }
        // load B tile 32x256 (8 float4 per thread)
#pragma unroll
        for (int i = 0; i < 8; i++) {
            int f4 = i * 256 + t;
            int bk = f4 >> 6;          // 64 float4 per 256-wide row
            int bc = (f4 & 63) << 2;
            float4 v;
            if (bc < 128) {
                v = *(const float4*)(Ws + (kk + bk) * 128 + bc);
                v.x *= ALPHA; v.y *= ALPHA; v.z *= ALPHA; v.w *= ALPHA;
            } else {
                v = *(const float4*)(Wd + (kk + bk) * 128 + (bc - 128));
                float b = 1.0f - ALPHA;
                v.x *= b; v.y *= b; v.z *= b; v.w *= b;
            }
            *(float4*)&Bs[bk][bc] = v;
        }
        __syncthreads();
#pragma unroll
        for (int k = 0; k < 32; k++) {
            float4 b0 = *(float4*)&Bs[k][tx * 4];
            float4 b1 = *(float4*)&Bs[k][128 + tx * 4];
            float a[8];
#pragma unroll
            for (int i = 0; i < 8; i++) a[i] = As[ty * 8 + i][k];
#pragma unroll
            for (int i = 0; i < 8; i++) {
                acc[i][0] += a[i] * b0.x; acc[i][1] += a[i] * b0.y;
                acc[i][2] += a[i] * b0.z; acc[i][3] += a[i] * b0.w;
                acc[i][4] += a[i] * b1.x; acc[i][5] += a[i] * b1.y;
                acc[i][6] += a[i] * b1.z; acc[i][7] += a[i] * b1.w;
            }
        }
        __syncthreads();
    }
#pragma unroll
    for (int i = 0; i < 8; i++) {
        int m = m0 + ty * 8 + i;
        if (m < M) {
            *(float4*)(g_y + (size_t)m * 256 + tx * 4) =
                make_float4(acc[i][0], acc[i][1], acc[i][2], acc[i][3]);
            *(float4*)(g_y + (size_t)m * 256 + 128 + tx * 4) =
                make_float4(acc[i][4], acc[i][5], acc[i][6], acc[i][7]);
        }
    }
}

// ---------------- gather: one warp per node ----------------------------------
__global__ __launch_bounds__(256) void k_gather(const float* __restrict__ bsrc,
                                                const float* __restrict__ bdst,
                                                float* __restrict__ out, int N) {
    int wid  = (blockIdx.x * blockDim.x + threadIdx.x) >> 5;
    int lane = threadIdx.x & 31;
    if (wid >= N) return;
    int n = wid;
    const float4* Y4 = (const float4*)g_y;

    float4 accf = make_float4(0.f, 0.f, 0.f, 0.f);
    float4 accb = make_float4(0.f, 0.f, 0.f, 0.f);

    int s  = g_off[n];
    int d  = g_deg[n];
    for (int j = s; j < s + d; j++) {
        int c = g_adj[j];
        float wc = g_dinv[NN + c];
        float4 v = Y4[(size_t)c * 64 + lane];      // fwd half of y[c]
        accf.x += wc * v.x; accf.y += wc * v.y;
        accf.z += wc * v.z; accf.w += wc * v.w;
    }
    int s2 = g_off[NN + n];
    int d2 = g_deg[NN + n];
    for (int j = s2; j < s2 + d2; j++) {
        int r = g_adj[j];
        float wr = g_dinv[r];
        float4 v = Y4[(size_t)r * 64 + 32 + lane]; // bwd half of y[r]
        accb.x += wr * v.x; accb.y += wr * v.y;
        accb.z += wr * v.z; accb.w += wr * v.w;
    }

    float df = g_dinv[n];        // d_out[n]^-1/2
    float db = g_dinv[NN + n];   // d_in[n]^-1/2
    float4 bs = ((const float4*)bsrc)[lane];
    float4 bd = ((const float4*)bdst)[lane];
    float4 o;
    o.x = ALPHA * bs.x + (1.0f - ALPHA) * bd.x + df * accf.x + db * accb.x;
    o.y = ALPHA * bs.y + (1.0f - ALPHA) * bd.y + df * accf.y + db * accb.y;
    o.z = ALPHA * bs.z + (1.0f - ALPHA) * bd.z + df * accf.z + db * accb.z;
    o.w = ALPHA * bs.w + (1.0f - ALPHA) * bd.w + df * accf.w + db * accb.w;
    ((float4*)out)[(size_t)n * 32 + lane] = o;
}

// ---------------- launch ------------------------------------------------------
extern "C" void kernel_launch(void* const* d_in, const int* in_sizes, int n_in,
                              void* d_out, int out_size) {
    const float* x    = (const float*)d_in[0];
    const int*   ei   = (const int*)d_in[1];
    const float* Wsrc = (const float*)d_in[2];
    const float* bsrc = (const float*)d_in[3];
    const float* Wdst = (const float*)d_in[4];
    const float* bdst = (const float*)d_in[5];
    float*       out  = (float*)d_out;

    int N = in_sizes[0] / 128;   // 50000
    int E = in_sizes[1] / 2;     // 800000
    if (N > NN || E > NE) return;

    int twoN = 2 * N;
    int nb   = (twoN + 511) / 512;   // scan blocks (196 <= 256)

    const int* row = ei;
    const int* col = ei + E;

    k_zero<<<(twoN + 255) / 256, 256>>>(twoN);
    k_count<<<(E + 255) / 256, 256>>>(row, col, E, N);
    k_scan1<<<nb, 512>>>(twoN);
    k_scan2<<<1, 256>>>(nb);
    k_scan3<<<nb, 512>>>(twoN);
    k_fill<<<(E + 255) / 256, 256>>>(row, col, E, N);
    k_gemm<<<(N + 63) / 64, 256>>>(x, Wsrc, Wdst, N);
    k_gather<<<(N * 32 + 255) / 256, 256>>>(bsrc, bdst, out, N);
}

// round 2
// speedup vs baseline: 1.0399x; 1.0399x over previous
#include <cuda_runtime.h>

#define NN 50000
#define NE 800000
#define ALPHA 0.5f

typedef unsigned long long u64;

// ---------------- scratch (device globals; no runtime allocation) -----------
__device__ int   g_deg[2 * NN];      // [0,NN): out-deg, [NN,2NN): in-deg
__device__ int   g_off[2 * NN];      // exclusive scan of g_deg
__device__ int   g_cur[2 * NN];      // fill cursors
__device__ float g_dinv[2 * NN];     // deg^-1/2 (0 if deg==0)
__device__ int   g_adj[2 * NE];      // fwd lists [0,E), bwd lists [E,2E)
__device__ float g_y[(size_t)NN * 256]; // [d_in*alpha*x@Wsrc | d_out*(1-a)*x@Wdst]
__device__ int   g_part[512];        // scan block totals

// ---------------- f32x2 helpers ----------------------------------------------
__device__ __forceinline__ u64 dup2(float a) {
    u64 r; asm("mov.b64 %0, {%1, %1};" : "=l"(r) : "f"(a)); return r;
}
__device__ __forceinline__ void fma2(u64& d, u64 a, u64 b) {
    asm("fma.rn.f32x2 %0, %1, %2, %0;" : "+l"(d) : "l"(a), "l"(b));
}
__device__ __forceinline__ float2 u2f(u64 v) {
    float2 f; asm("mov.b64 {%0, %1}, %2;" : "=f"(f.x), "=f"(f.y) : "l"(v)); return f;
}

// ---------------- init / degree count ---------------------------------------
__global__ void k_zero(int twoN) {
    int i = blockIdx.x * blockDim.x + threadIdx.x;
    if (i < twoN) g_deg[i] = 0;
}

__global__ void k_count(const int* __restrict__ row, const int* __restrict__ col,
                        int E, int N) {
    int e = blockIdx.x * blockDim.x + threadIdx.x;
    if (e < E) {
        atomicAdd(&g_deg[row[e]], 1);
        atomicAdd(&g_deg[N + col[e]], 1);
    }
}

// ---------------- block exclusive scan helper --------------------------------
__device__ __forceinline__ int block_exscan(int val, int nwarps) {
    __shared__ int ws[16];
    int lane = threadIdx.x & 31, w = threadIdx.x >> 5;
    int inc = val;
#pragma unroll
    for (int d = 1; d < 32; d <<= 1) {
        int t = __shfl_up_sync(0xffffffffu, inc, d);
        if (lane >= d) inc += t;
    }
    if (lane == 31) ws[w] = inc;
    __syncthreads();
    if (w == 0) {
        int s = (lane < nwarps) ? ws[lane] : 0;
#pragma unroll
        for (int d = 1; d < 16; d <<= 1) {
            int t = __shfl_up_sync(0xffffffffu, s, d);
            if (lane >= d) s += t;
        }
        if (lane < nwarps) ws[lane] = s;
    }
    __syncthreads();
    int pre = (w > 0) ? ws[w - 1] : 0;
    return pre + inc - val;
}

__global__ void k_scan1(int twoN) {  // 512 threads
    int i = blockIdx.x * 512 + threadIdx.x;
    int v = (i < twoN) ? g_deg[i] : 0;
    int ex = block_exscan(v, 16);
    if (i < twoN) g_off[i] = ex;
    if (threadIdx.x == 511) g_part[blockIdx.x] = ex + v;
}

// Each block reduces the totals of all preceding blocks, then finalizes offsets.
__global__ void k_scan23(int twoN) {  // 512 threads
    __shared__ int ws[17];
    int t = threadIdx.x;
    int v = (t < (int)blockIdx.x) ? g_part[t] : 0;  // gridDim <= 512
    int s = v;
#pragma unroll
    for (int d = 16; d; d >>= 1) s += __shfl_down_sync(0xffffffffu, s, d);
    if ((t & 31) == 0) ws[t >> 5] = s;
    __syncthreads();
    if (t < 16) {
        int x = ws[t];
#pragma unroll
        for (int d = 8; d; d >>= 1) x += __shfl_down_sync(0x0000ffffu, x, d);
        if (t == 0) ws[16] = x;
    }
    __syncthreads();
    int base = ws[16];

    int i = blockIdx.x * 512 + t;
    if (i < twoN) {
        int o = g_off[i] + base;
        g_off[i] = o;
        g_cur[i] = o;
        int d = g_deg[i];
        g_dinv[i] = (d > 0) ? rsqrtf((float)d) : 0.0f;
    }
}

// ---------------- CSR fill ----------------------------------------------------
__global__ void k_fill(const int* __restrict__ row, const int* __restrict__ col,
                       int E, int N) {
    int e = blockIdx.x * blockDim.x + threadIdx.x;
    if (e < E) {
        int r = row[e], c = col[e];
        int p = atomicAdd(&g_cur[r], 1);
        g_adj[p] = c;
        int q = atomicAdd(&g_cur[N + c], 1);
        g_adj[q] = r;
    }
}

// ---------------- GEMM: y = x @ [a*Wsrc | (1-a)*Wdst], rows pre-scaled -------
__global__ __launch_bounds__(256) void k_gemm(const float* __restrict__ X,
                                              const float* __restrict__ Ws,
                                              const float* __restrict__ Wd,
                                              int M, int N) {
    __shared__ __align__(16) float As[64][32];
    __shared__ __align__(16) float Bs[32][256];
    int t  = threadIdx.x;
    int tx = t & 31;   // column group
    int ty = t >> 5;   // row group
    int m0 = blockIdx.x * 64;
    u64 acc[8][4];
#pragma unroll
    for (int i = 0; i < 8; i++)
#pragma unroll
        for (int j = 0; j < 4; j++) acc[i][j] = 0ull;

    for (int kk = 0; kk < 128; kk += 32) {
        // load A tile 64x32 (2 float4 per thread)
#pragma unroll
        for (int i = 0; i < 2; i++) {
            int f4 = i * 256 + t;
            int ar = f4 >> 3, ac = (f4 & 7) << 2;
            float4 v = make_float4(0.f, 0.f, 0.f, 0.f);
            int m = m0 + ar;
            if (m < M) v = *(const float4*)(X + (size_t)m * 128 + kk + ac);
            *(float4*)&As[ar][ac] = v;
        }
        // load B tile 32x256 (8 float4 per thread), alpha folded in
#pragma unroll
        for (int i = 0; i < 8; i++) {
            int f4 = i * 256 + t;
            int bk = f4 >> 6;
            int bc = (f4 & 63) << 2;
            float4 v;
            if (bc < 128) {
                v = *(const float4*)(Ws + (kk + bk) * 128 + bc);
                v.x *= ALPHA; v.y *= ALPHA; v.z *= ALPHA; v.w *= ALPHA;
            } else {
                v = *(const float4*)(Wd + (kk + bk) * 128 + (bc - 128));
                float b = 1.0f - ALPHA;
                v.x *= b; v.y *= b; v.z *= b; v.w *= b;
            }
            *(float4*)&Bs[bk][bc] = v;
        }
        __syncthreads();
#pragma unroll
        for (int k = 0; k < 32; k++) {
            ulonglong2 b0 = *(const ulonglong2*)&Bs[k][tx * 4];
            ulonglong2 b1 = *(const ulonglong2*)&Bs[k][128 + tx * 4];
#pragma unroll
            for (int i = 0; i < 8; i++) {
                u64 a2 = dup2(As[ty * 8 + i][k]);
                fma2(acc[i][0], a2, b0.x);
                fma2(acc[i][1], a2, b0.y);
                fma2(acc[i][2], a2, b1.x);
                fma2(acc[i][3], a2, b1.y);
            }
        }
        __syncthreads();
    }
#pragma unroll
    for (int i = 0; i < 8; i++) {
        int m = m0 + ty * 8 + i;
        if (m < M) {
            float sf = g_dinv[N + m];   // d_in[m]^-1/2 scales fwd half
            float sb = g_dinv[m];       // d_out[m]^-1/2 scales bwd half
            float2 p0 = u2f(acc[i][0]), p1 = u2f(acc[i][1]);
            float2 p2 = u2f(acc[i][2]), p3 = u2f(acc[i][3]);
            float4 o0 = make_float4(p0.x * sf, p0.y * sf, p1.x * sf, p1.y * sf);
            float4 o1 = make_float4(p2.x * sb, p2.y * sb, p3.x * sb, p3.y * sb);
            *(float4*)(g_y + (size_t)m * 256 + tx * 4) = o0;
            *(float4*)(g_y + (size_t)m * 256 + 128 + tx * 4) = o1;
        }
    }
}

// ---------------- gather: one warp per node, pure adds ------------------------
__global__ __launch_bounds__(256) void k_gather(const float* __restrict__ bsrc,
                                                const float* __restrict__ bdst,
                                                float* __restrict__ out, int N) {
    int wid  = (blockIdx.x * blockDim.x + threadIdx.x) >> 5;
    int lane = threadIdx.x & 31;
    if (wid >= N) return;
    int n = wid;
    const float4* __restrict__ Y4 = (const float4*)g_y;

    float4 accf = make_float4(0.f, 0.f, 0.f, 0.f);
    float4 accb = make_float4(0.f, 0.f, 0.f, 0.f);

    int s = g_off[n], e = s + g_deg[n];
    int j = s;
    for (; j + 2 <= e; j += 2) {
        int c0 = g_adj[j], c1 = g_adj[j + 1];
        float4 v0 = Y4[(size_t)c0 * 64 + lane];
        float4 v1 = Y4[(size_t)c1 * 64 + lane];
        accf.x += v0.x + v1.x; accf.y += v0.y + v1.y;
        accf.z += v0.z + v1.z; accf.w += v0.w + v1.w;
    }
    if (j < e) {
        int c = g_adj[j];
        float4 v = Y4[(size_t)c * 64 + lane];
        accf.x += v.x; accf.y += v.y; accf.z += v.z; accf.w += v.w;
    }

    int s2 = g_off[N + n], e2 = s2 + g_deg[N + n];
    j = s2;
    for (; j + 2 <= e2; j += 2) {
        int r0 = g_adj[j], r1 = g_adj[j + 1];
        float4 v0 = Y4[(size_t)r0 * 64 + 32 + lane];
        float4 v1 = Y4[(size_t)r1 * 64 + 32 + lane];
        accb.x += v0.x + v1.x; accb.y += v0.y + v1.y;
        accb.z += v0.z + v1.z; accb.w += v0.w + v1.w;
    }
    if (j < e2) {
        int r = g_adj[j];
        float4 v = Y4[(size_t)r * 64 + 32 + lane];
        accb.x += v.x; accb.y += v.y; accb.z += v.z; accb.w += v.w;
    }

    float df = g_dinv[n];        // d_out[n]^-1/2
    float db = g_dinv[N + n];    // d_in[n]^-1/2
    float4 bs = ((const float4*)bsrc)[lane];
    float4 bd = ((const float4*)bdst)[lane];
    float4 o;
    o.x = ALPHA * bs.x + (1.0f - ALPHA) * bd.x + df * accf.x + db * accb.x;
    o.y = ALPHA * bs.y + (1.0f - ALPHA) * bd.y + df * accf.y + db * accb.y;
    o.z = ALPHA * bs.z + (1.0f - ALPHA) * bd.z + df * accf.z + db * accb.z;
    o.w = ALPHA * bs.w + (1.0f - ALPHA) * bd.w + df * accf.w + db * accb.w;
    ((float4*)out)[(size_t)n * 32 + lane] = o;
}

// ---------------- launch ------------------------------------------------------
extern "C" void kernel_launch(void* const* d_in, const int* in_sizes, int n_in,
                              void* d_out, int out_size) {
    const float* x    = (const float*)d_in[0];
    const int*   ei   = (const int*)d_in[1];
    const float* Wsrc = (const float*)d_in[2];
    const float* bsrc = (const float*)d_in[3];
    const float* Wdst = (const float*)d_in[4];
    const float* bdst = (const float*)d_in[5];
    float*       out  = (float*)d_out;

    int N = in_sizes[0] / 128;   // 50000
    int E = in_sizes[1] / 2;     // 800000
    if (N > NN || E > NE) return;

    int twoN = 2 * N;
    int nb   = (twoN + 511) / 512;   // 196 blocks <= 512

    const int* row = ei;
    const int* col = ei + E;

    k_zero<<<(twoN + 255) / 256, 256>>>(twoN);
    k_count<<<(E + 255) / 256, 256>>>(row, col, E, N);
    k_scan1<<<nb, 512>>>(twoN);
    k_scan23<<<nb, 512>>>(twoN);
    k_fill<<<(E + 255) / 256, 256>>>(row, col, E, N);
    k_gemm<<<(N + 63) / 64, 256>>>(x, Wsrc, Wdst, N, N);
    k_gather<<<(N * 32 + 255) / 256, 256>>>(bsrc, bdst, out, N);
}

// round 5
// speedup vs baseline: 1.5429x; 1.4837x over previous
#include <cuda_runtime.h>
#include <cuda_bf16.h>
#include <cstdint>

#define NN 50000
#define NE 800000
#define ALPHA 0.5f

// ---------------- scratch (device globals) -----------------------------------
__device__ int   g_deg[2 * NN];
__device__ int   g_off[2 * NN];
__device__ int   g_cur[2 * NN];
__device__ float g_dinv[2 * NN];
__device__ int   g_adj[2 * NE];
__device__ float g_y[(size_t)NN * 256];
__device__ int   g_part[512];

__device__ __forceinline__ uint32_t smem_u32(const void* p) {
    uint32_t a;
    asm("{ .reg .u64 t; cvta.to.shared.u64 t, %1; cvt.u32.u64 %0, t; }" : "=r"(a) : "l"(p));
    return a;
}
__device__ __forceinline__ void ldsm_x4(uint32_t* r, uint32_t addr) {
    asm volatile("ldmatrix.sync.aligned.m8n8.x4.shared.b16 {%0,%1,%2,%3}, [%4];"
        : "=r"(r[0]), "=r"(r[1]), "=r"(r[2]), "=r"(r[3]) : "r"(addr));
}
__device__ __forceinline__ void ldsm_x4_t(uint32_t* r, uint32_t addr) {
    asm volatile("ldmatrix.sync.aligned.m8n8.x4.trans.shared.b16 {%0,%1,%2,%3}, [%4];"
        : "=r"(r[0]), "=r"(r[1]), "=r"(r[2]), "=r"(r[3]) : "r"(addr));
}
__device__ __forceinline__ void mma_bf16(float* c, const uint32_t* a, const uint32_t* b) {
    asm volatile(
        "mma.sync.aligned.m16n8k16.row.col.f32.bf16.bf16.f32 "
        "{%0,%1,%2,%3}, {%4,%5,%6,%7}, {%8,%9}, {%0,%1,%2,%3};"
        : "+f"(c[0]), "+f"(c[1]), "+f"(c[2]), "+f"(c[3])
        : "r"(a[0]), "r"(a[1]), "r"(a[2]), "r"(a[3]), "r"(b[0]), "r"(b[1]));
}

// ---------------- prep kernels -----------------------------------------------
__global__ void k_zero(int twoN) {
    int i = blockIdx.x * blockDim.x + threadIdx.x;
    if (i < twoN) g_deg[i] = 0;
}
__global__ void k_count(const int* __restrict__ row, const int* __restrict__ col,
                        int E, int N) {
    int e = blockIdx.x * blockDim.x + threadIdx.x;
    if (e < E) {
        atomicAdd(&g_deg[row[e]], 1);
        atomicAdd(&g_deg[N + col[e]], 1);
    }
}
__device__ __forceinline__ int block_exscan(int val, int nwarps) {
    __shared__ int ws[16];
    int lane = threadIdx.x & 31, w = threadIdx.x >> 5;
    int inc = val;
#pragma unroll
    for (int d = 1; d < 32; d <<= 1) {
        int t = __shfl_up_sync(0xffffffffu, inc, d);
        if (lane >= d) inc += t;
    }
    if (lane == 31) ws[w] = inc;
    __syncthreads();
    if (w == 0) {
        int s = (lane < nwarps) ? ws[lane] : 0;
#pragma unroll
        for (int d = 1; d < 16; d <<= 1) {
            int t = __shfl_up_sync(0xffffffffu, s, d);
            if (lane >= d) s += t;
        }
        if (lane < nwarps) ws[lane] = s;
    }
    __syncthreads();
    int pre = (w > 0) ? ws[w - 1] : 0;
    return pre + inc - val;
}
__global__ void k_scan1(int twoN) {
    int i = blockIdx.x * 512 + threadIdx.x;
    int v = (i < twoN) ? g_deg[i] : 0;
    int ex = block_exscan(v, 16);
    if (i < twoN) g_off[i] = ex;
    if (threadIdx.x == 511) g_part[blockIdx.x] = ex + v;
}
__global__ void k_scan23(int twoN) {
    __shared__ int ws[17];
    int t = threadIdx.x;
    int v = (t < (int)blockIdx.x) ? g_part[t] : 0;
    int s = v;
#pragma unroll
    for (int d = 16; d; d >>= 1) s += __shfl_down_sync(0xffffffffu, s, d);
    if ((t & 31) == 0) ws[t >> 5] = s;
    __syncthreads();
    if (t < 16) {
        int x = ws[t];
#pragma unroll
        for (int d = 8; d; d >>= 1) x += __shfl_down_sync(0x0000ffffu, x, d);
        if (t == 0) ws[16] = x;
    }
    __syncthreads();
    int base = ws[16];
    int i = blockIdx.x * 512 + t;
    if (i < twoN) {
        int o = g_off[i] + base;
        g_off[i] = o;
        g_cur[i] = o;
        int d = g_deg[i];
        g_dinv[i] = (d > 0) ? rsqrtf((float)d) : 0.0f;
    }
}
__global__ void k_fill(const int* __restrict__ row, const int* __restrict__ col,
                       int E, int N) {
    int e = blockIdx.x * blockDim.x + threadIdx.x;
    if (e < E) {
        int r = row[e], c = col[e];
        int p = atomicAdd(&g_cur[r], 1);
        g_adj[p] = c;
        int q = atomicAdd(&g_cur[N + c], 1);
        g_adj[q] = r;
    }
}

// ---------------- HMMA bf16-split GEMM ---------------------------------------
// Asm[m][k] halves, row stride 256B, swizzle: off = m*256 + ((k*2) ^ ((m&7)<<4))
// Bsm[k][n] halves (n=256), row stride 512B, off = k*512 + ((n*2) ^ ((k&7)<<4))
#define SA_HI 0
#define SA_LO 32768
#define SB_HI 65536
#define SB_LO 131072
#define SM_TOT 196608

__global__ __launch_bounds__(256, 1) void k_gemm_mma(const float* __restrict__ X,
                                                     const float* __restrict__ Ws,
                                                     const float* __restrict__ Wd,
                                                     int M, int N) {
    extern __shared__ char sm[];
    uint32_t sb = smem_u32(sm);
    int tid = threadIdx.x, lane = tid & 31, wid = tid >> 5;
    int m0 = blockIdx.x * 128;

    // --- A convert: x[m0:m0+128, 0:128] -> bf16 hi/lo ---
#pragma unroll
    for (int it = 0; it < 16; it++) {
        int i = it * 256 + tid;
        int row = i >> 5, c4 = (i & 31) << 2;
        int m = m0 + row;
        float4 v = make_float4(0.f, 0.f, 0.f, 0.f);
        if (m < M) v = *(const float4*)(X + (size_t)m * 128 + c4);
        uint32_t off = (uint32_t)row * 256u + (((uint32_t)c4 * 2u) ^ (((uint32_t)row & 7u) << 4));
        __nv_bfloat16 h[4], l2[4];
        float vv[4] = {v.x, v.y, v.z, v.w};
#pragma unroll
        for (int jj = 0; jj < 4; jj++) {
            h[jj]  = __float2bfloat16(vv[jj]);
            l2[jj] = __float2bfloat16(vv[jj] - __bfloat162float(h[jj]));
        }
        *(uint2*)(sm + SA_HI + off) = *(uint2*)h;
        *(uint2*)(sm + SA_LO + off) = *(uint2*)l2;
    }

    // --- B convert: Bsm[k][0:128] = a*Ws[k][:], Bsm[k][128:256] = (1-a)*Wd[k][:] ---
#pragma unroll
    for (int it = 0; it < 32; it++) {
        int i = it * 256 + tid;
        int k = i >> 6, n4 = (i & 63) << 2;
        float4 v; float sc;
        if (n4 < 128) { v = *(const float4*)(Ws + (size_t)k * 128 + n4); sc = ALPHA; }
        else          { v = *(const float4*)(Wd + (size_t)k * 128 + (n4 - 128)); sc = 1.0f - ALPHA; }
        float vv[4] = {v.x * sc, v.y * sc, v.z * sc, v.w * sc};
        uint32_t off = (uint32_t)k * 512u + (((uint32_t)n4 * 2u) ^ (((uint32_t)k & 7u) << 4));
        __nv_bfloat16 h[4], l2[4];
#pragma unroll
        for (int jj = 0; jj < 4; jj++) {
            h[jj]  = __float2bfloat16(vv[jj]);
            l2[jj] = __float2bfloat16(vv[jj] - __bfloat162float(h[jj]));
        }
        *(uint2*)(sm + SB_HI + off) = *(uint2*)h;
        *(uint2*)(sm + SB_LO + off) = *(uint2*)l2;
    }
    __syncthreads();

    int wm = wid >> 2, wn = wid & 3;      // warp grid 2 (M) x 4 (N)
    int g = lane >> 3, j = lane & 7;
    int arow_l = ((g & 1) << 3) + j;       // A: row-in-tilepair
    int akc16  = (g >> 1) << 4;            // A: k byte sel (0 or 16)
    int bkrow_l = ((g & 1) << 3) + j;      // B: k row-in-frag
    int bnc8   = (g >> 1) << 3;            // B: n sel (0 or 8)

#pragma unroll
    for (int np = 0; np < 2; np++) {
        int n0w = np * 128 + wn * 32;
        float acc[4][4][4];
#pragma unroll
        for (int a = 0; a < 4; a++)
#pragma unroll
            for (int b = 0; b < 4; b++)
#pragma unroll
                for (int c = 0; c < 4; c++) acc[a][b][c] = 0.f;

#pragma unroll
        for (int ks = 0; ks < 8; ks++) {
            uint32_t ah[4][4], al[4][4];
#pragma unroll
            for (int fm = 0; fm < 4; fm++) {
                int row = wm * 64 + fm * 16 + arow_l;
                uint32_t ao = (uint32_t)row * 256u
                            + (((uint32_t)(ks * 32 + akc16)) ^ ((uint32_t)j << 4));
                ldsm_x4(ah[fm], sb + SA_HI + ao);
                ldsm_x4(al[fm], sb + SA_LO + ao);
            }
            uint32_t bh[4][2], bl[4][2];
#pragma unroll
            for (int fn2 = 0; fn2 < 2; fn2++) {
                int krow = ks * 16 + bkrow_l;
                uint32_t bo = (uint32_t)krow * 512u
                            + (((uint32_t)((n0w + fn2 * 16 + bnc8) * 2)) ^ ((uint32_t)j << 4));
                uint32_t r[4];
                ldsm_x4_t(r, sb + SB_HI + bo);
                bh[fn2 * 2][0] = r[0]; bh[fn2 * 2][1] = r[1];
                bh[fn2 * 2 + 1][0] = r[2]; bh[fn2 * 2 + 1][1] = r[3];
                ldsm_x4_t(r, sb + SB_LO + bo);
                bl[fn2 * 2][0] = r[0]; bl[fn2 * 2][1] = r[1];
                bl[fn2 * 2 + 1][0] = r[2]; bl[fn2 * 2 + 1][1] = r[3];
            }
#pragma unroll
            for (int fm = 0; fm < 4; fm++)
#pragma unroll
                for (int fn = 0; fn < 4; fn++) {
                    mma_bf16(acc[fm][fn], ah[fm], bh[fn]);
                    mma_bf16(acc[fm][fn], ah[fm], bl[fn]);
                    mma_bf16(acc[fm][fn], al[fm], bh[fn]);
                }
        }

        // epilogue: scale rows by neighbor-side deg^-1/2, write g_y
#pragma unroll
        for (int fm = 0; fm < 4; fm++) {
            int r0 = m0 + wm * 64 + fm * 16 + (lane >> 2);
            int r1 = r0 + 8;
            float s0 = 0.f, s1 = 0.f;
            if (r0 < M) s0 = (np == 0) ? g_dinv[N + r0] : g_dinv[r0];
            if (r1 < M) s1 = (np == 0) ? g_dinv[N + r1] : g_dinv[r1];
#pragma unroll
            for (int fn = 0; fn < 4; fn++) {
                int col = n0w + fn * 8 + (lane & 3) * 2;
                if (r0 < M) {
                    float2 o = make_float2(acc[fm][fn][0] * s0, acc[fm][fn][1] * s0);
                    *(float2*)(g_y + (size_t)r0 * 256 + col) = o;
                }
                if (r1 < M) {
                    float2 o = make_float2(acc[fm][fn][2] * s1, acc[fm][fn][3] * s1);
                    *(float2*)(g_y + (size_t)r1 * 256 + col) = o;
                }
            }
        }
    }
}

// ---------------- gather ------------------------------------------------------
__global__ __launch_bounds__(256) void k_gather(const float* __restrict__ bsrc,
                                                const float* __restrict__ bdst,
                                                float* __restrict__ out, int N) {
    int wid  = (blockIdx.x * blockDim.x + threadIdx.x) >> 5;
    int lane = threadIdx.x & 31;
    if (wid >= N) return;
    int n = wid;
    const float4* __restrict__ Y4 = (const float4*)g_y;

    float4 accf = make_float4(0.f, 0.f, 0.f, 0.f);
    float4 accb = make_float4(0.f, 0.f, 0.f, 0.f);

    int s = g_off[n], e = s + g_deg[n];
    int j = s;
    for (; j + 2 <= e; j += 2) {
        int c0 = g_adj[j], c1 = g_adj[j + 1];
        float4 v0 = Y4[(size_t)c0 * 64 + lane];
        float4 v1 = Y4[(size_t)c1 * 64 + lane];
        accf.x += v0.x + v1.x; accf.y += v0.y + v1.y;
        accf.z += v0.z + v1.z; accf.w += v0.w + v1.w;
    }
    if (j < e) {
        int c = g_adj[j];
        float4 v = Y4[(size_t)c * 64 + lane];
        accf.x += v.x; accf.y += v.y; accf.z += v.z; accf.w += v.w;
    }

    int s2 = g_off[N + n], e2 = s2 + g_deg[N + n];
    j = s2;
    for (; j + 2 <= e2; j += 2) {
        int r0 = g_adj[j], r1 = g_adj[j + 1];
        float4 v0 = Y4[(size_t)r0 * 64 + 32 + lane];
        float4 v1 = Y4[(size_t)r1 * 64 + 32 + lane];
        accb.x += v0.x + v1.x; accb.y += v0.y + v1.y;
        accb.z += v0.z + v1.z; accb.w += v0.w + v1.w;
    }
    if (j < e2) {
        int r = g_adj[j];
        float4 v = Y4[(size_t)r * 64 + 32 + lane];
        accb.x += v.x; accb.y += v.y; accb.z += v.z; accb.w += v.w;
    }

    float df = g_dinv[n];
    float db = g_dinv[N + n];
    float4 bs = ((const float4*)bsrc)[lane];
    float4 bd = ((const float4*)bdst)[lane];
    float4 o;
    o.x = ALPHA * bs.x + (1.0f - ALPHA) * bd.x + df * accf.x + db * accb.x;
    o.y = ALPHA * bs.y + (1.0f - ALPHA) * bd.y + df * accf.y + db * accb.y;
    o.z = ALPHA * bs.z + (1.0f - ALPHA) * bd.z + df * accf.z + db * accb.z;
    o.w = ALPHA * bs.w + (1.0f - ALPHA) * bd.w + df * accf.w + db * accb.w;
    ((float4*)out)[(size_t)n * 32 + lane] = o;
}

// ---------------- launch ------------------------------------------------------
extern "C" void kernel_launch(void* const* d_in, const int* in_sizes, int n_in,
                              void* d_out, int out_size) {
    const float* x    = (const float*)d_in[0];
    const int*   ei   = (const int*)d_in[1];
    const float* Wsrc = (const float*)d_in[2];
    const float* bsrc = (const float*)d_in[3];
    const float* Wdst = (const float*)d_in[4];
    const float* bdst = (const float*)d_in[5];
    float*       out  = (float*)d_out;

    int N = in_sizes[0] / 128;
    int E = in_sizes[1] / 2;
    if (N > NN || E > NE) return;

    int twoN = 2 * N;
    int nb   = (twoN + 511) / 512;

    const int* row = ei;
    const int* col = ei + E;

    cudaFuncSetAttribute(k_gemm_mma, cudaFuncAttributeMaxDynamicSharedMemorySize, SM_TOT);

    k_zero<<<(twoN + 255) / 256, 256>>>(twoN);
    k_count<<<(E + 255) / 256, 256>>>(row, col, E, N);
    k_scan1<<<nb, 512>>>(twoN);
    k_scan23<<<nb, 512>>>(twoN);
    k_fill<<<(E + 255) / 256, 256>>>(row, col, E, N);
    k_gemm_mma<<<(N + 127) / 128, 256, SM_TOT>>>(x, Wsrc, Wdst, N, N);
    k_gather<<<(N * 32 + 255) / 256, 256>>>(bsrc, bdst, out, N);
}